// round 5
// baseline (speedup 1.0000x reference)
#include <cuda_runtime.h>
#include <math.h>

#define NOBJ  2048
#define EMBED 256
#define NHD   8
#define NP    32
#define HD    32
#define FFN_D 1024
#define HIMG  160
#define WIMG  160
#define HW    (HIMG*WIMG)

// ---- scratch (device globals; no allocations allowed) ----
__device__ float g_loc [NOBJ*NHD*NP*2];   // unnormalized sample coords (ix,iy)
__device__ float g_attn[NOBJ*EMBED];      // attention output (pre w_out)
__device__ float g_x1  [NOBJ*EMBED];      // after w_out + residual (pre LN1)
__device__ float g_x1ln[NOBJ*EMBED];      // after LN1
__device__ float g_hid [NOBJ*FFN_D];      // relu(x@w1+b1)
__device__ float g_x2  [NOBJ*EMBED];      // pre LN2

// ============================================================================
// SGEMM: C(MxN) = A(MxK) @ B(KxN)  row-major, 64x64 tile, 128 threads, 4x8 micro
// EPI 0: offsets -> sample coords   EPI 1: +bias +res   EPI 2: relu(+bias)
// EPI 3: +bias +res
// ============================================================================
template<int EPI>
__global__ __launch_bounds__(128) void sgemm_k(
    const float* __restrict__ A, const float* __restrict__ B,
    const float* __restrict__ bias, const float* __restrict__ res,
    float* __restrict__ C, int M, int N, int K,
    const float* __restrict__ xy, const float* __restrict__ strd)
{
    __shared__ float As[16][68];   // [k][m], padded (16B-aligned rows)
    __shared__ float Bs[16][68];   // [k][n]

    const int tid = threadIdx.x;
    const int tx = tid & 7;        // 0..7  -> 8 cols of 8? no: col group
    const int ty = tid >> 3;       // 0..15 -> row group
    const int row0 = blockIdx.y * 64;
    const int col0 = blockIdx.x * 64;

    float acc[4][8];
#pragma unroll
    for (int i = 0; i < 4; i++)
#pragma unroll
        for (int j = 0; j < 8; j++) acc[i][j] = 0.f;

    for (int kt = 0; kt < K; kt += 16) {
#pragma unroll
        for (int l = 0; l < 2; l++) {
            int idx = tid + l * 128;              // 0..255
            // A tile: 64 rows x 16 k  (256 float4)
            int am = idx >> 2;                    // 0..63
            int ak = (idx & 3) << 2;              // 0,4,8,12
            float4 av = *(const float4*)(A + (size_t)(row0 + am) * K + kt + ak);
            As[ak + 0][am] = av.x;
            As[ak + 1][am] = av.y;
            As[ak + 2][am] = av.z;
            As[ak + 3][am] = av.w;
            // B tile: 16 k x 64 n
            int bk = idx >> 4;                    // 0..15
            int bn = (idx & 15) << 2;             // 0..60
            float4 bv = *(const float4*)(B + (size_t)(kt + bk) * N + col0 + bn);
            *(float4*)&Bs[bk][bn] = bv;
        }
        __syncthreads();
#pragma unroll
        for (int k = 0; k < 16; k++) {
            float4 a4 = *(const float4*)&As[k][ty * 4];
            float4 b0 = *(const float4*)&Bs[k][tx * 8];
            float4 b1 = *(const float4*)&Bs[k][tx * 8 + 4];
            float av[4] = {a4.x, a4.y, a4.z, a4.w};
            float bv[8] = {b0.x, b0.y, b0.z, b0.w, b1.x, b1.y, b1.z, b1.w};
#pragma unroll
            for (int i = 0; i < 4; i++)
#pragma unroll
                for (int j = 0; j < 8; j++) acc[i][j] += av[i] * bv[j];
        }
        __syncthreads();
    }

#pragma unroll
    for (int i = 0; i < 4; i++) {
        int row = row0 + ty * 4 + i;
        float st = 0.f, bx = 0.f, by = 0.f;
        if (EPI == 0) { st = strd[row]; bx = xy[2 * row]; by = xy[2 * row + 1]; }
#pragma unroll
        for (int j = 0; j < 8; j++) {
            int col = col0 + tx * 8 + j;
            float v = acc[i][j] + bias[col];
            size_t oidx = (size_t)row * N + col;
            if (EPI == 0) {
                int c = col & 1;
                float base = c ? by : bx;
                float loc = base + v * st;
                float gn  = loc * (2.0f / 640.0f) - 1.0f;
                float iv  = ((gn + 1.0f) * 160.0f - 1.0f) * 0.5f;
                C[oidx] = iv;
            } else if (EPI == 1 || EPI == 3) {
                C[oidx] = v + res[oidx];
            } else { // EPI == 2
                C[oidx] = fmaxf(v, 0.f);
            }
        }
    }
}

// ============================================================================
// Sampler: 1 block per object (256 thr = 8 warps), warp = head, lane = point.
// Bilinear gather k/v (border), x2d (border), mask (zeros); attention softmax.
// ============================================================================
__global__ __launch_bounds__(256) void sampler_k(
    const float* __restrict__ query, const float* __restrict__ key,
    const float* __restrict__ val,   const float* __restrict__ x2d,
    const float* __restrict__ maskp, const int*   __restrict__ imgind,
    const float* __restrict__ loc,
    float* __restrict__ outv, float* __restrict__ outa,
    float* __restrict__ outm, float* __restrict__ outx,
    float* __restrict__ attn)
{
    __shared__ float qs  [NHD][HD];
    __shared__ float vsm [NHD][HD][NP + 1];  // [h][d][p], pad 33
    __shared__ float asms[NHD][NP];

    const int n   = blockIdx.x;
    const int tid = threadIdx.x;
    const int h   = tid >> 5;
    const int p   = tid & 31;

    qs[h][p] = query[(size_t)n * EMBED + h * HD + p];
    const int img = imgind[n];

    float2 l2 = ((const float2*)loc)[((size_t)n * NHD + h) * NP + p];
    float ix = l2.x, iy = l2.y;
    float x0f = floorf(ix), y0f = floorf(iy);
    float wx1 = ix - x0f,   wy1 = iy - y0f;
    float wx0 = 1.f - wx1,  wy0 = 1.f - wy1;
    int x0 = (int)x0f, y0 = (int)y0f;
    int x1i = x0 + 1,  y1i = y0 + 1;
    int xc0 = min(max(x0, 0), WIMG - 1), xc1 = min(max(x1i, 0), WIMG - 1);
    int yc0 = min(max(y0, 0), HIMG - 1), yc1 = min(max(y1i, 0), HIMG - 1);
    float w00 = wx0 * wy0, w10 = wx1 * wy0, w01 = wx0 * wy1, w11 = wx1 * wy1;
    int o00 = yc0 * WIMG + xc0, o10 = yc0 * WIMG + xc1;
    int o01 = yc1 * WIMG + xc0, o11 = yc1 * WIMG + xc1;

    const float* kb = key + ((size_t)img * EMBED + h * HD) * HW;
    const float* vb = val + ((size_t)img * EMBED + h * HD) * HW;

    __syncwarp();

    float a = 0.f;
    float* outvb = outv + (((size_t)n * NHD + h) * HD) * NP + p;
#pragma unroll 4
    for (int d = 0; d < HD; d++) {
        const float* kp = kb + d * HW;
        float ks = w00 * kp[o00] + w10 * kp[o10] + w01 * kp[o01] + w11 * kp[o11];
        a += qs[h][d] * ks;
        const float* vp = vb + d * HW;
        float vs = w00 * vp[o00] + w10 * vp[o10] + w01 * vp[o01] + w11 * vp[o11];
        vsm[h][d][p] = vs;
        outvb[d * NP] = vs;                       // v_samples[n,h,d,p] coalesced
    }
    a *= 0.17677669529663687f;                    // 1/sqrt(32)
    size_t baseNP = ((size_t)n * NHD + h) * NP + p;
    outa[baseNP] = a;                             // pre-softmax a_samples

    // mask: zeros padding
    bool vx0 = (x0  >= 0) && (x0  < WIMG), vx1 = (x1i >= 0) && (x1i < WIMG);
    bool vy0 = (y0  >= 0) && (y0  < HIMG), vy1 = (y1i >= 0) && (y1i < HIMG);
    const float* mb = maskp + (size_t)img * HW;
    float mval = 0.f;
    if (vx0 && vy0) mval += w00 * mb[o00];
    if (vx1 && vy0) mval += w10 * mb[o10];
    if (vx0 && vy1) mval += w01 * mb[o01];
    if (vx1 && vy1) mval += w11 * mb[o11];
    outm[baseNP] = mval;

    // x2d: border padding, 2 channels
    const float* xb0 = x2d + (size_t)img * 2 * HW;
    const float* xb1 = xb0 + HW;
    float xs0 = w00 * xb0[o00] + w10 * xb0[o10] + w01 * xb0[o01] + w11 * xb0[o11];
    float xs1 = w00 * xb1[o00] + w10 * xb1[o10] + w01 * xb1[o01] + w11 * xb1[o11];
    size_t xbase = (((size_t)n * NHD + h) * 2) * NP + p;
    outx[xbase]      = xs0;
    outx[xbase + NP] = xs1;

    // softmax over 32 points (warp-wide), then * mask
    float mx = a;
#pragma unroll
    for (int o = 16; o; o >>= 1) mx = fmaxf(mx, __shfl_xor_sync(0xffffffffu, mx, o));
    float e = expf(a - mx);
    float ssum = e;
#pragma unroll
    for (int o = 16; o; o >>= 1) ssum += __shfl_xor_sync(0xffffffffu, ssum, o);
    float asv = e / ssum * mval;
    asms[h][p] = asv;
    __syncwarp();

    // out[n,h,d] = sum_p a_sm[p] * v[p][d]  (lane = d)
    const int d = p;
    float o = 0.f;
#pragma unroll
    for (int pp = 0; pp < NP; pp++) o += asms[h][pp] * vsm[h][d][pp];
    attn[(size_t)n * EMBED + h * HD + d] = o;
}

// ============================================================================
// LayerNorm over 256 features; 1 block (256 thr) per row
// ============================================================================
__global__ __launch_bounds__(256) void ln_k(
    const float* __restrict__ x, const float* __restrict__ g,
    const float* __restrict__ b, float* __restrict__ y)
{
    __shared__ float red[8];
    const int r = blockIdx.x, t = threadIdx.x;
    float v = x[(size_t)r * EMBED + t];

    float s = v;
#pragma unroll
    for (int o = 16; o; o >>= 1) s += __shfl_xor_sync(0xffffffffu, s, o);
    if ((t & 31) == 0) red[t >> 5] = s;
    __syncthreads();
    float tot = 0.f;
#pragma unroll
    for (int i = 0; i < 8; i++) tot += red[i];
    float mean = tot * (1.f / 256.f);
    float d = v - mean;
    __syncthreads();

    s = d * d;
#pragma unroll
    for (int o = 16; o; o >>= 1) s += __shfl_xor_sync(0xffffffffu, s, o);
    if ((t & 31) == 0) red[t >> 5] = s;
    __syncthreads();
    tot = 0.f;
#pragma unroll
    for (int i = 0; i < 8; i++) tot += red[i];
    float inv = rsqrtf(tot * (1.f / 256.f) + 1e-5f);
    y[(size_t)r * EMBED + t] = d * inv * g[t] + b[t];
}

// ============================================================================
extern "C" void kernel_launch(void* const* d_in, const int* in_sizes, int n_in,
                              void* d_out, int out_size)
{
    const float* query   = (const float*)d_in[0];
    const float* obj_emb = (const float*)d_in[1];
    const float* key_f   = (const float*)d_in[2];
    const float* value   = (const float*)d_in[3];
    const float* x2d     = (const float*)d_in[4];
    const float* maskp   = (const float*)d_in[5];
    const float* xy      = (const float*)d_in[6];
    const float* strides = (const float*)d_in[7];
    const int*   imgind  = (const int*  )d_in[8];
    const float* w_off   = (const float*)d_in[9];
    const float* b_off   = (const float*)d_in[10];
    const float* w_out   = (const float*)d_in[11];
    const float* b_out   = (const float*)d_in[12];
    const float* ln1g    = (const float*)d_in[13];
    const float* ln1b    = (const float*)d_in[14];
    const float* w1      = (const float*)d_in[15];
    const float* b1      = (const float*)d_in[16];
    const float* w2      = (const float*)d_in[17];
    const float* b2      = (const float*)d_in[18];
    const float* ln2g    = (const float*)d_in[19];
    const float* ln2b    = (const float*)d_in[20];

    float* out  = (float*)d_out;                 // (N,256)
    float* outv = out  + (size_t)NOBJ * EMBED;   // (N,8,32,32)  v_samples
    float* outa = outv + (size_t)NOBJ * NHD * HD * NP;   // (N,8,1,32)
    float* outm = outa + (size_t)NOBJ * NHD * NP;        // (N,8,1,32)
    float* outx = outm + (size_t)NOBJ * NHD * NP;        // (N,8,2,32)

    float *p_loc, *p_attn, *p_x1, *p_x1ln, *p_hid, *p_x2;
    cudaGetSymbolAddress((void**)&p_loc,  g_loc);
    cudaGetSymbolAddress((void**)&p_attn, g_attn);
    cudaGetSymbolAddress((void**)&p_x1,   g_x1);
    cudaGetSymbolAddress((void**)&p_x1ln, g_x1ln);
    cudaGetSymbolAddress((void**)&p_hid,  g_hid);
    cudaGetSymbolAddress((void**)&p_x2,   g_x2);

    // 1) offsets GEMM -> sample coords
    sgemm_k<0><<<dim3(512 / 64, NOBJ / 64), 128>>>(
        obj_emb, w_off, b_off, nullptr, p_loc, NOBJ, 512, EMBED, xy, strides);

    // 2) gather + attention + sample outputs
    sampler_k<<<NOBJ, 256>>>(query, key_f, value, x2d, maskp, imgind, p_loc,
                             outv, outa, outm, outx, p_attn);

    // 3) w_out GEMM + bias + residual(obj_emb)
    sgemm_k<1><<<dim3(EMBED / 64, NOBJ / 64), 128>>>(
        p_attn, w_out, b_out, obj_emb, p_x1, NOBJ, EMBED, EMBED, nullptr, nullptr);

    // 4) LN1
    ln_k<<<NOBJ, 256>>>(p_x1, ln1g, ln1b, p_x1ln);

    // 5) FFN up + relu
    sgemm_k<2><<<dim3(FFN_D / 64, NOBJ / 64), 128>>>(
        p_x1ln, w1, b1, nullptr, p_hid, NOBJ, FFN_D, EMBED, nullptr, nullptr);

    // 6) FFN down + bias + residual(x1ln)
    sgemm_k<3><<<dim3(EMBED / 64, NOBJ / 64), 128>>>(
        p_hid, w2, b2, p_x1ln, p_x2, NOBJ, EMBED, FFN_D, nullptr, nullptr);

    // 7) LN2 -> final out
    ln_k<<<NOBJ, 256>>>(p_x2, ln2g, ln2b, out);
}